// round 9
// baseline (speedup 1.0000x reference)
#include <cuda_runtime.h>

// EdgesToGlobalsAggregator: segment-sum of edges [TOTAL_EDGES, 128] fp32 into
// [num_graphs, 128] fp32. R8: 256-bit loads (ld.global.nc.v8.f32 -> LDG.E.256).
// Warp = 2 rows x 16 slots of 8 floats; 4 independent 1KB warp-loads in flight.
// Per-block prefix of n_edge kept from R2 (champion structure).

#define D_FEAT 128
#define NTHREADS 256

struct F8 { float v[8]; };

__device__ __forceinline__ void ldg256(F8& d, const float* p) {
    asm volatile("ld.global.nc.v8.f32 {%0,%1,%2,%3,%4,%5,%6,%7}, [%8];"
                 : "=f"(d.v[0]), "=f"(d.v[1]), "=f"(d.v[2]), "=f"(d.v[3]),
                   "=f"(d.v[4]), "=f"(d.v[5]), "=f"(d.v[6]), "=f"(d.v[7])
                 : "l"(p));
}

__device__ __forceinline__ void acc8(F8& a, const F8& b) {
    #pragma unroll
    for (int i = 0; i < 8; i++) a.v[i] += b.v[i];
}

__global__ __launch_bounds__(NTHREADS, 4)
void segment_sum_v8_kernel(const float* __restrict__ edges,
                           const int* __restrict__ n_edge,
                           int num_graphs,
                           float* __restrict__ out) {
    const int g    = blockIdx.x;
    const int tid  = threadIdx.x;
    const int lane = tid & 31;
    const int warp = tid >> 5;        // 0..7
    const int slot = lane & 15;       // 8-float feature slot 0..15
    const int par  = lane >> 4;       // row parity 0/1

    // ---- per-block exclusive prefix: start = sum(n_edge[0..g-1]), mine = n_edge[g]
    __shared__ int s_warp[8];
    __shared__ int s_start, s_mine;

    int local = 0;
    for (int i = tid; i < g; i += NTHREADS)
        local += __ldg(&n_edge[i]);
    #pragma unroll
    for (int off = 16; off > 0; off >>= 1)
        local += __shfl_down_sync(0xFFFFFFFFu, local, off);
    if (lane == 0) s_warp[warp] = local;
    __syncthreads();
    if (tid == 0) {
        int acc = 0;
        #pragma unroll
        for (int i = 0; i < 8; i++) acc += s_warp[i];
        s_start = acc;
        s_mine  = __ldg(&n_edge[g]);
    }
    __syncthreads();

    const int start = s_start;
    const int nrows = s_mine;

    // this thread's row offset within each 16-row step, and feature byte offset
    const int rsub = warp * 2 + par;          // 0..15
    const float* __restrict__ base = edges + (size_t)start * D_FEAT + slot * 8;

    F8 a0, a1, a2, a3;
    #pragma unroll
    for (int i = 0; i < 8; i++) { a0.v[i] = 0.f; a1.v[i] = 0.f; a2.v[i] = 0.f; a3.v[i] = 0.f; }

    int rb = 0;
    // main: 4 independent LDG.256 in flight, 64 rows per step
    for (; rb + 64 <= nrows; rb += 64) {
        F8 x0, x1, x2, x3;
        ldg256(x0, base + (size_t)(rb + rsub)      * D_FEAT);
        ldg256(x1, base + (size_t)(rb + rsub + 16) * D_FEAT);
        ldg256(x2, base + (size_t)(rb + rsub + 32) * D_FEAT);
        ldg256(x3, base + (size_t)(rb + rsub + 48) * D_FEAT);
        acc8(a0, x0); acc8(a1, x1); acc8(a2, x2); acc8(a3, x3);
    }
    // 16-row tail steps
    for (; rb + 16 <= nrows; rb += 16) {
        F8 x;
        ldg256(x, base + (size_t)(rb + rsub) * D_FEAT);
        acc8(a0, x);
    }
    // remainder rows (< 16)
    if (rb + rsub < nrows) {
        F8 x;
        ldg256(x, base + (size_t)(rb + rsub) * D_FEAT);
        acc8(a0, x);
    }

    acc8(a0, a1); acc8(a0, a2); acc8(a0, a3);

    // ---- reduce 16 partials (8 warps x 2 parities) per slot ----
    __shared__ float sp[16][16][8];   // [warp*2+par][slot][elem] = 8KB
    #pragma unroll
    for (int i = 0; i < 8; i++) sp[rsub][slot][i] = a0.v[i];
    __syncthreads();

    if (tid < D_FEAT) {
        const int cs = tid >> 3;      // slot
        const int ce = tid & 7;       // elem within slot
        float s = 0.f;
        #pragma unroll
        for (int i = 0; i < 16; i++) s += sp[i][cs][ce];
        out[(size_t)g * D_FEAT + tid] = s;
    }
}

extern "C" void kernel_launch(void* const* d_in, const int* in_sizes, int n_in,
                              void* d_out, int out_size) {
    const float* edges  = (const float*)d_in[0];
    const int*   n_edge = (const int*)d_in[1];
    const int num_graphs = in_sizes[1];          // 1024

    segment_sum_v8_kernel<<<num_graphs, NTHREADS>>>(
        edges, n_edge, num_graphs, (float*)d_out);
}

// round 10
// speedup vs baseline: 1.0632x; 1.0632x over previous
#include <cuda_runtime.h>

// EdgesToGlobalsAggregator: segment-sum of edges [TOTAL_EDGES, 128] fp32 into
// [num_graphs, 128] fp32.
// R9: R1's main kernel (plain LDG.128, no per-CTA prefix -> best measured DRAM
// busy 89.8%) + a minimal one-block scan kernel (1 barrier, ~1us) instead of
// R1's 20-barrier Hillis-Steele (2.2us).

#define MAX_GRAPHS 1024
#define D_FEAT 128
#define VEC (D_FEAT / 4)   // 32 float4 per row
#define NTHREADS 256

__device__ int g_offsets[MAX_GRAPHS + 1];

// One block, 256 threads: thread t serially sums n_edge[4t..4t+3], warp-scan
// of the 256 thread-sums (2-level, 1 barrier), then each thread writes its 4
// exclusive offsets.
__global__ __launch_bounds__(NTHREADS)
void scan_offsets_kernel(const int* __restrict__ n_edge, int num_graphs) {
    const int tid  = threadIdx.x;
    const int lane = tid & 31;
    const int warp = tid >> 5;

    int i0 = 4 * tid;
    int v0 = (i0 + 0 < num_graphs) ? __ldg(&n_edge[i0 + 0]) : 0;
    int v1 = (i0 + 1 < num_graphs) ? __ldg(&n_edge[i0 + 1]) : 0;
    int v2 = (i0 + 2 < num_graphs) ? __ldg(&n_edge[i0 + 2]) : 0;
    int v3 = (i0 + 3 < num_graphs) ? __ldg(&n_edge[i0 + 3]) : 0;
    int loc = v0 + v1 + v2 + v3;

    // inclusive warp scan of loc
    int sc = loc;
    #pragma unroll
    for (int off = 1; off < 32; off <<= 1) {
        int n = __shfl_up_sync(0xFFFFFFFFu, sc, off);
        if (lane >= off) sc += n;
    }

    __shared__ int wsum[8];
    if (lane == 31) wsum[warp] = sc;
    __syncthreads();

    int wbase = 0;
    #pragma unroll
    for (int i = 0; i < 8; i++) if (i < warp) wbase += wsum[i];

    int run = wbase + sc - loc;   // exclusive prefix of this thread's chunk
    if (i0 + 0 <= num_graphs) g_offsets[i0 + 0] = run;  run += v0;
    if (i0 + 1 <= num_graphs) g_offsets[i0 + 1] = run;  run += v1;
    if (i0 + 2 <= num_graphs) g_offsets[i0 + 2] = run;  run += v2;
    if (i0 + 3 <= num_graphs) g_offsets[i0 + 3] = run;  run += v3;
    if (tid == NTHREADS - 1 && 4 * NTHREADS <= MAX_GRAPHS)
        g_offsets[4 * NTHREADS] = run;
    if (tid == NTHREADS - 1) g_offsets[num_graphs] = run;  // ensure total present
}

__global__ __launch_bounds__(NTHREADS, 4)
void segment_sum_kernel(const float4* __restrict__ edges, float4* __restrict__ out) {
    const int g    = blockIdx.x;
    const int lane = threadIdx.x & 31;   // float4 feature slot 0..31
    const int warp = threadIdx.x >> 5;   // row-slice 0..7

    const int start = g_offsets[g];
    const int nrows = g_offsets[g + 1] - start;

    const float4* __restrict__ base = edges + (size_t)start * VEC;

    float4 a0 = make_float4(0.f, 0.f, 0.f, 0.f);
    float4 a1 = make_float4(0.f, 0.f, 0.f, 0.f);
    float4 a2 = make_float4(0.f, 0.f, 0.f, 0.f);
    float4 a3 = make_float4(0.f, 0.f, 0.f, 0.f);

    int r = warp;
    // 4-way unrolled main loop: 4 independent LDG.128 in flight per iter.
    for (; r + 24 < nrows; r += 32) {
        float4 v0 = base[(size_t)(r)      * VEC + lane];
        float4 v1 = base[(size_t)(r + 8)  * VEC + lane];
        float4 v2 = base[(size_t)(r + 16) * VEC + lane];
        float4 v3 = base[(size_t)(r + 24) * VEC + lane];
        a0.x += v0.x; a0.y += v0.y; a0.z += v0.z; a0.w += v0.w;
        a1.x += v1.x; a1.y += v1.y; a1.z += v1.z; a1.w += v1.w;
        a2.x += v2.x; a2.y += v2.y; a2.z += v2.z; a2.w += v2.w;
        a3.x += v3.x; a3.y += v3.y; a3.z += v3.z; a3.w += v3.w;
    }
    // tail
    for (; r < nrows; r += 8) {
        float4 v = base[(size_t)r * VEC + lane];
        a0.x += v.x; a0.y += v.y; a0.z += v.z; a0.w += v.w;
    }

    a0.x += a1.x + a2.x + a3.x;
    a0.y += a1.y + a2.y + a3.y;
    a0.z += a1.z + a2.z + a3.z;
    a0.w += a1.w + a2.w + a3.w;

    __shared__ float4 sp[8][32];
    sp[warp][lane] = a0;
    __syncthreads();

    if (warp == 0) {
        float4 s = sp[0][lane];
        #pragma unroll
        for (int i = 1; i < 8; i++) {
            float4 v = sp[i][lane];
            s.x += v.x; s.y += v.y; s.z += v.z; s.w += v.w;
        }
        out[(size_t)g * VEC + lane] = s;
    }
}

extern "C" void kernel_launch(void* const* d_in, const int* in_sizes, int n_in,
                              void* d_out, int out_size) {
    const float* edges  = (const float*)d_in[0];
    const int*   n_edge = (const int*)d_in[1];
    const int num_graphs = in_sizes[1];          // 1024

    scan_offsets_kernel<<<1, NTHREADS>>>(n_edge, num_graphs);
    segment_sum_kernel<<<num_graphs, NTHREADS>>>((const float4*)edges, (float4*)d_out);
}